// round 14
// baseline (speedup 1.0000x reference)
#include <cuda_runtime.h>
#include <math.h>

#define N_NODES 200
#define NM1     199
#define E_TOT   39800
#define TE      128

typedef unsigned long long u64;

__device__ __forceinline__ u64 pack2(float lo, float hi) {
    u64 r; asm("mov.b64 %0,{%1,%2};" : "=l"(r) : "f"(lo), "f"(hi)); return r;
}
__device__ __forceinline__ void unpack2(u64 v, float& lo, float& hi) {
    asm("mov.b64 {%0,%1},%2;" : "=f"(lo), "=f"(hi) : "l"(v));
}
__device__ __forceinline__ void ffma2(u64& d, u64 a, u64 b) {
    asm("fma.rn.f32x2 %0,%1,%2,%0;" : "+l"(d) : "l"(a), "l"(b));
}

// ---------------- scratch ----------------
__device__ __align__(16) float g_part[16 * 200 * 512];
__device__ __align__(16) float g_wgp [4 * 257 * 512];
__device__ __align__(16) float g_h1[200 * 512];
__device__ __align__(16) float g_h2[200 * 256];
__device__ __align__(16) float g_Gt[200 * 512];      // [n][o*128+h]
__device__ __align__(16) float g_c [200 * 4];
__device__ __align__(16) float g_P [200 * 4];
__device__ __align__(16) float g_msg[E_TOT * 4];
__device__ __align__(16) float g_W3G [257 * 512];    // row 256 = bias
__device__ __align__(16) float g_W3CH[257 * 12];
__device__ __align__(16) float g_Ae[200 * 256];      // [n][u]
__device__ __align__(16) float g_Be[200 * 256];      // [n][u]
__device__ __align__(16) float g_w3b3[257 * 1024];
__device__ __align__(16) float g_wp2p[1024 * 512];

// ---------------- 256-thread GEMM tile: 64 rows x 128 cols ----------------
__device__ void gemm_tile64(const float* __restrict__ A, int lda,
                            const float* __restrict__ B, int ldb,
                            float* __restrict__ outp, int ldo, int M,
                            int col0, int row0, int k0, int k1,
                            const float* __restrict__ bias, float* sh, int modeGt) {
    float* As = sh;           // [16][68]
    float* Bs = sh + 1088;    // [16][128]
    int t = threadIdx.x;
    int tx = t & 31, ty = t >> 5;
    u64 acc[4][4];
#pragma unroll
    for (int p = 0; p < 4; p++)
#pragma unroll
        for (int c = 0; c < 4; c++) acc[p][c] = pack2(0.f, 0.f);
    int am = t >> 2;
    int ak = (t & 3) * 4;
    int bk = t >> 4;
    int bn = (t & 15) * 8;
    unsigned sa = (unsigned)__cvta_generic_to_shared(As + ty * 8);

    for (int kt = k0; kt < k1; kt += 16) {
        {
            int gr = row0 + am;
            float4 av = make_float4(0.f, 0.f, 0.f, 0.f);
            if (gr < M) av = *(const float4*)(A + (size_t)gr * lda + kt + ak);
            As[(ak + 0) * 68 + am] = av.x;
            As[(ak + 1) * 68 + am] = av.y;
            As[(ak + 2) * 68 + am] = av.z;
            As[(ak + 3) * 68 + am] = av.w;
        }
        {
            const float4* bp = (const float4*)(B + (size_t)(kt + bk) * ldb + col0 + bn);
            *(float4*)(Bs + bk * 128 + bn)     = bp[0];
            *(float4*)(Bs + bk * 128 + bn + 4) = bp[1];
        }
        __syncthreads();
#pragma unroll
        for (int kk = 0; kk < 16; kk++) {
            u64 a01, a23, a45, a67;
            asm("ld.shared.v2.u64 {%0,%1},[%2];"
                : "=l"(a01), "=l"(a23) : "r"(sa + kk * 272));
            asm("ld.shared.v2.u64 {%0,%1},[%2];"
                : "=l"(a45), "=l"(a67) : "r"(sa + kk * 272 + 16));
            float4 b4 = *(float4*)(Bs + kk * 128 + tx * 4);
            u64 bx = pack2(b4.x, b4.x), by = pack2(b4.y, b4.y);
            u64 bz = pack2(b4.z, b4.z), bw = pack2(b4.w, b4.w);
            ffma2(acc[0][0], a01, bx); ffma2(acc[1][0], a23, bx);
            ffma2(acc[2][0], a45, bx); ffma2(acc[3][0], a67, bx);
            ffma2(acc[0][1], a01, by); ffma2(acc[1][1], a23, by);
            ffma2(acc[2][1], a45, by); ffma2(acc[3][1], a67, by);
            ffma2(acc[0][2], a01, bz); ffma2(acc[1][2], a23, bz);
            ffma2(acc[2][2], a45, bz); ffma2(acc[3][2], a67, bz);
            ffma2(acc[0][3], a01, bw); ffma2(acc[1][3], a23, bw);
            ffma2(acc[2][3], a45, bw); ffma2(acc[3][3], a67, bw);
        }
        __syncthreads();
    }
#pragma unroll
    for (int p = 0; p < 4; p++) {
        int gr0 = row0 + ty * 8 + p * 2, gr1 = gr0 + 1;
#pragma unroll
        for (int c = 0; c < 4; c++) {
            float lo, hi; unpack2(acc[p][c], lo, hi);
            int col = col0 + tx * 4 + c;
            float bv = bias ? bias[col] : 0.f;
            lo += bv; hi += bv;
            int oc = modeGt ? ((col & 3) * 128 + (col >> 2)) : col;
            if (gr0 < M) outp[(size_t)gr0 * ldo + oc] = lo;
            if (gr1 < M) outp[(size_t)gr1 * ldo + oc] = hi;
        }
    }
}

// ======== k_p0: gemm1 partials | permute wp2 | prep | W3CH | w3b3 copy ========
__global__ void k_p0(const float* __restrict__ roi,  const float* __restrict__ w1,
                     const float* __restrict__ w3,   const float* __restrict__ b3,
                     const float* __restrict__ wp2,  const float* __restrict__ bp2,
                     const float* __restrict__ wi,   const float* __restrict__ rootw,
                     const float* __restrict__ bbox, const float* __restrict__ dirs,
                     const float* __restrict__ we1,  const float* __restrict__ be1) {
    __shared__ __align__(16) float sh[3136];
    int task = blockIdx.x, t = threadIdx.x;
    if (task < 256) {
        int col0 = (task & 3) * 128;
        int row0 = ((task >> 2) & 3) * 64;
        int z = task >> 4;
        gemm_tile64(roi, 2048, w1, 512, g_part + (size_t)z * 102400, 512,
                    N_NODES, col0, row0, z * 128, z * 128 + 128, nullptr, sh, 0);
    } else if (task < 1280) {
        int base = (task - 256) * 512;
#pragma unroll
        for (int q = 0; q < 2; q++) {
            int idx = base + t + q * 256;
            int i = idx >> 9, r = idx & 511;
            g_wp2p[idx] = wp2[(size_t)(r >> 2) * 4096 + i * 4 + (r & 3)];
        }
    } else if (task < 1480) {
        int n = task - 1280;
        float attr[8];
#pragma unroll
        for (int k = 0; k < 4; k++) attr[k] = bbox[n * 4 + k] * (1.0f / 1024.0f);
#pragma unroll
        for (int k = 0; k < 4; k++) attr[4 + k] = dirs[n * 4 + k];
        int u = t;
        float a = be1[u], b = 0.f;
#pragma unroll
        for (int k = 0; k < 8; k++) {
            a += attr[k] * we1[k * 256 + u];
            b += attr[k] * we1[(8 + k) * 256 + u];
        }
        g_Ae[n * 256 + u] = a;
        g_Be[n * 256 + u] = b;
    } else if (task < 1737) {
        int gr = task - 1480;
        float acc[12];
#pragma unroll
        for (int c = 0; c < 12; c++) acc[c] = 0.f;
        for (int i = t; i < 1024; i += 256) {
            float a = (gr < 256) ? w3[(size_t)gr * 1024 + i] : b3[i];
            float4 p = *(const float4*)(bp2 + i * 4);
            float4 q = *(const float4*)(wi + i * 4);
            float4 r = *(const float4*)(rootw + i * 4);
            acc[0] += a * p.x; acc[1] += a * p.y; acc[2]  += a * p.z; acc[3]  += a * p.w;
            acc[4] += a * q.x; acc[5] += a * q.y; acc[6]  += a * q.z; acc[7]  += a * q.w;
            acc[8] += a * r.x; acc[9] += a * r.y; acc[10] += a * r.z; acc[11] += a * r.w;
        }
#pragma unroll
        for (int c = 0; c < 12; c++) sh[t * 12 + c] = acc[c];
        __syncthreads();
        for (int s = 128; s > 0; s >>= 1) {
            if (t < s)
#pragma unroll
                for (int c = 0; c < 12; c++) sh[t * 12 + c] += sh[(t + s) * 12 + c];
            __syncthreads();
        }
        if (t < 12) g_W3CH[gr * 12 + t] = sh[t];
    } else {
        int idx = (task - 1737) * 256 + t;
        if (idx < 257 * 1024) {
            int row = idx >> 10, col = idx & 1023;
            g_w3b3[idx] = (row < 256) ? w3[(size_t)row * 1024 + col] : b3[col];
        }
    }
}

// ======== k_p1: h1 reduce | W3G split-K partials ========
__global__ void k_p1(const float* __restrict__ b1) {
    __shared__ __align__(16) float sh[3136];
    int task = blockIdx.x, t = threadIdx.x;
    if (task < 400) {
        int idx = task * 256 + t;
        float s = 0.f;
#pragma unroll
        for (int z = 0; z < 16; z++) s += g_part[(size_t)z * 102400 + idx];
        g_h1[idx] = fmaxf(s + b1[idx & 511], 0.f);
    } else {
        int w = task - 400;
        int col0 = (w & 3) * 128;
        int row0 = ((w >> 2) % 5) * 64;
        int z = w / 20;
        gemm_tile64(g_w3b3, 1024, g_wp2p, 512, g_wgp + (size_t)z * 131584, 512,
                    257, col0, row0, z * 256, z * 256 + 256, nullptr, sh, 0);
    }
}

// ======== k_p2: gemm2 partials | W3G reduce ========
__global__ void k_p2(const float* __restrict__ w2) {
    __shared__ __align__(16) float sh[3136];
    int task = blockIdx.x, t = threadIdx.x;
    if (task < 64) {
        int col0 = (task & 1) * 128;
        int row0 = ((task >> 1) & 3) * 64;
        int z = task >> 3;
        gemm_tile64(g_h1, 512, w2, 256, g_part + (size_t)z * 51200, 256,
                    N_NODES, col0, row0, z * 64, z * 64 + 64, nullptr, sh, 0);
    } else {
        int idx = (task - 64) * 256 + t;
        if (idx < 257 * 512) {
            float s = 0.f;
#pragma unroll
            for (int z = 0; z < 4; z++) s += g_wgp[(size_t)z * 131584 + idx];
            g_W3G[idx] = s;
        }
    }
}

// ======== k_edge_a: h1 + layer2 + layer3-in-registers -> e4 (launch #4) ========
__global__ void k_edge_a(const float* __restrict__ pri,
                         const float* __restrict__ we2, const float* __restrict__ be2,
                         const float* __restrict__ we3, const float* __restrict__ be3,
                         float* __restrict__ edge_out) {
    // ubuf: s_h1[32][136] (4352 f) + s_w[32][64] (2048 f) = 6400 f = 25.6 KB
    __shared__ __align__(16) float ubuf[6400];
    __shared__ __align__(16) float s_A[512];
    __shared__ int s_src[TE], s_dst[TE];

    float* s_h1 = ubuf;
    float* s_w  = ubuf + 4352;

    int t = threadIdx.x;
    int base = blockIdx.x * TE;
    int src0 = base / NM1;
    int last = min(base + TE - 1, E_TOT - 1);
    int src1 = last / NM1;

    if (t < TE) {
        int ge = base + t;
        int i = src0, j = 0;
        if (ge < E_TOT) {
            i = ge / NM1;
            int r = ge - i * NM1;
            j = (r < i) ? r : r + 1;
        }
        s_src[t] = i; s_dst[t] = j;
    }
    if (t < 128) {
        int row = t >> 6, k4 = (t & 63) * 4;
        *(float4*)(s_A + row * 256 + k4) =
            *(const float4*)(g_Ae + (row ? src1 : src0) * 256 + k4);
    }
    __syncthreads();

    // thread tile: v0 = (t&15)*4 (4 outs), e0 = (t>>4)*8 (8 edges, uniform per 16-lane group)
    int tv = t & 15, teg = t >> 4;
    int v0 = tv * 4, e0 = teg * 8;

    // we3 rows for this thread's v-group (12 regs)
    float w3r[4][3];
#pragma unroll
    for (int c = 0; c < 4; c++)
#pragma unroll
        for (int w = 0; w < 3; w++) w3r[c][w] = we3[(v0 + c) * 3 + w];

    u64 acc[4][4];
    {
        float4 b4 = *(const float4*)(be2 + v0);
        acc[0][0] = acc[1][0] = acc[2][0] = acc[3][0] = pack2(b4.x, b4.x);
        acc[0][1] = acc[1][1] = acc[2][1] = acc[3][1] = pack2(b4.y, b4.y);
        acc[0][2] = acc[1][2] = acc[2][2] = acc[3][2] = pack2(b4.z, b4.z);
        acc[0][3] = acc[1][3] = acc[2][3] = acc[3][3] = pack2(b4.w, b4.w);
    }
    unsigned hb = (unsigned)__cvta_generic_to_shared(s_h1 + e0);

    for (int uc = 0; uc < 8; uc++) {
        // h1 build: float4 gather from g_Be[n][u], conflict-free scalar STS
#pragma unroll
        for (int k = 0; k < 4; k++) {
            int q = t + k * 256;
            int e = q & 127;
            int u4 = (q >> 7) * 4;
            int U = uc * 32 + u4;
            int ge = base + e;
            float4 bv = make_float4(0.f, 0.f, 0.f, 0.f);
            float4 av = make_float4(0.f, 0.f, 0.f, 0.f);
            if (ge < E_TOT) {
                bv = *(const float4*)(g_Be + s_dst[e] * 256 + U);
                int aoff = (s_src[e] == src0) ? 0 : 256;
                av = *(const float4*)(s_A + aoff + U);
            }
            s_h1[(u4 + 0) * 136 + e] = fmaxf(av.x + bv.x, 0.f);
            s_h1[(u4 + 1) * 136 + e] = fmaxf(av.y + bv.y, 0.f);
            s_h1[(u4 + 2) * 136 + e] = fmaxf(av.z + bv.z, 0.f);
            s_h1[(u4 + 3) * 136 + e] = fmaxf(av.w + bv.w, 0.f);
        }
        // we2 chunk
#pragma unroll
        for (int k = 0; k < 2; k++) {
            int r = t + k * 256;
            int u = r >> 4, v4 = (r & 15) * 4;
            *(float4*)(s_w + u * 64 + v4) =
                *(const float4*)(we2 + (uc * 32 + u) * 64 + v4);
        }
        __syncthreads();
#pragma unroll 8
        for (int jj = 0; jj < 32; jj++) {
            u64 a01, a23, a45, a67;
            asm("ld.shared.v2.u64 {%0,%1},[%2];"
                : "=l"(a01), "=l"(a23) : "r"(hb + jj * 544));
            asm("ld.shared.v2.u64 {%0,%1},[%2];"
                : "=l"(a45), "=l"(a67) : "r"(hb + jj * 544 + 16));
            float4 w4 = *(float4*)(s_w + jj * 64 + v0);
            u64 bx = pack2(w4.x, w4.x), by = pack2(w4.y, w4.y);
            u64 bz = pack2(w4.z, w4.z), bw = pack2(w4.w, w4.w);
            ffma2(acc[0][0], a01, bx); ffma2(acc[1][0], a23, bx);
            ffma2(acc[2][0], a45, bx); ffma2(acc[3][0], a67, bx);
            ffma2(acc[0][1], a01, by); ffma2(acc[1][1], a23, by);
            ffma2(acc[2][1], a45, by); ffma2(acc[3][1], a67, by);
            ffma2(acc[0][2], a01, bz); ffma2(acc[1][2], a23, bz);
            ffma2(acc[2][2], a45, bz); ffma2(acc[3][2], a67, bz);
            ffma2(acc[0][3], a01, bw); ffma2(acc[1][3], a23, bw);
            ffma2(acc[2][3], a45, bw); ffma2(acc[3][3], a67, bw);
        }
        __syncthreads();
    }

    // ---- layer3 partials in registers: part[8e][3w] ----
    float part[8][3];
#pragma unroll
    for (int e = 0; e < 8; e++)
#pragma unroll
        for (int w = 0; w < 3; w++) part[e][w] = 0.f;
#pragma unroll
    for (int p = 0; p < 4; p++) {
#pragma unroll
        for (int c = 0; c < 4; c++) {
            float lo, hi; unpack2(acc[p][c], lo, hi);
            lo = fmaxf(lo, 0.f); hi = fmaxf(hi, 0.f);
#pragma unroll
            for (int w = 0; w < 3; w++) {
                part[2 * p][w]     += lo * w3r[c][w];
                part[2 * p + 1][w] += hi * w3r[c][w];
            }
        }
    }
    // butterfly across the 16 v-group lanes
#pragma unroll
    for (int off = 1; off < 16; off <<= 1) {
#pragma unroll
        for (int e = 0; e < 8; e++)
#pragma unroll
            for (int w = 0; w < 3; w++)
                part[e][w] += __shfl_xor_sync(0xffffffffu, part[e][w], off);
    }
    // lanes 0..7 of each 16-lane group: finalize one edge each
    if (tv < 8) {
        int e = e0 + tv;
        int ge = base + e;
        if (ge < E_TOT) {
            float a0 = be3[0] + part[tv][0];
            float a1 = be3[1] + part[tv][1];
            float a2 = be3[2] + part[tv][2];
            float s0 = 1.f / (1.f + expf(-a0));
            float s1 = 1.f / (1.f + expf(-a1));
            float s2 = 1.f / (1.f + expf(-a2));
            float hp = (pri[s_src[e]] > pri[s_dst[e]]) ? 1.f : 0.f;
            *(float4*)(edge_out + ge * 4) = make_float4(s0, s1, s2, hp);
        }
    }
}

// ======== k_p3: h2 reduce ========
__global__ void k_p3(const float* __restrict__ b2) {
    int idx = blockIdx.x * 256 + threadIdx.x;
    float s = 0.f;
#pragma unroll
    for (int z = 0; z < 8; z++) s += g_part[(size_t)z * 51200 + idx];
    g_h2[idx] = fmaxf(s + b2[idx & 255], 0.f);
}

// ======== k_p4: Gt = (h2 @ W3G + bias) transposed | heads ========
__global__ void k_p4(const float* __restrict__ bi, float* __restrict__ out2) {
    __shared__ __align__(16) float sh[3136];
    int task = blockIdx.x, t = threadIdx.x;
    if (task < 16) {
        int col0 = (task & 3) * 128;
        int row0 = (task >> 2) * 64;
        gemm_tile64(g_h2, 256, g_W3G, 512, g_Gt, 512, N_NODES,
                    col0, row0, 0, 256, g_W3G + 256 * 512, sh, 1);
    } else {
        int n = task - 16;
        float a = g_h2[n * 256 + t];
        float4 w0  = *(const float4*)(g_W3CH + t * 12);
        float4 w1v = *(const float4*)(g_W3CH + t * 12 + 4);
        float4 w2v = *(const float4*)(g_W3CH + t * 12 + 8);
        float acc[12] = {a*w0.x, a*w0.y, a*w0.z, a*w0.w,
                         a*w1v.x, a*w1v.y, a*w1v.z, a*w1v.w,
                         a*w2v.x, a*w2v.y, a*w2v.z, a*w2v.w};
#pragma unroll
        for (int q = 0; q < 12; q++) sh[t * 12 + q] = acc[q];
        __syncthreads();
        for (int s = 128; s > 0; s >>= 1) {
            if (t < s)
#pragma unroll
                for (int q = 0; q < 12; q++) sh[t * 12 + q] += sh[(t + s) * 12 + q];
            __syncthreads();
        }
        if (t == 0) {
#pragma unroll
            for (int o = 0; o < 4; o++) {
                g_c[n * 4 + o] = sh[o] + g_W3CH[256 * 12 + o];
                float cv = sh[4 + o] + g_W3CH[256 * 12 + 4 + o] + bi[o];
                out2[n * 4 + o] = 1.f / (1.f + expf(-cv));
                g_P[n * 4 + o] = sh[8 + o] + g_W3CH[256 * 12 + 8 + o];
            }
        }
    }
}

// ======== k_edge_b: heh recompute + msg contraction ========
__global__ void k_edge_b(const float* __restrict__ e4in,
                         const float* __restrict__ wp1, const float* __restrict__ bp1) {
    __shared__ __align__(16) float s_G[1024];
    __shared__ __align__(16) float s_wp1b[640];
    __shared__ __align__(16) float s_e4[TE * 4];
    __shared__ __align__(16) float s_red[256 * 4];
    __shared__ int s_srcf[TE];

    int t = threadIdx.x;
    int base = blockIdx.x * TE;
    int src0 = base / NM1;
    int last = min(base + TE - 1, E_TOT - 1);
    int src1 = last / NM1;
    int nvalid = (E_TOT - base < TE) ? (E_TOT - base) : TE;

    if (t < TE) {
        int ge = base + t;
        s_srcf[t] = (ge < E_TOT) ? (ge / NM1) : src0;
    }
    {
        int idx0 = t * 4;
        int row = (idx0 < 512) ? src0 : src1;
        *(float4*)(s_G + idx0) = *(const float4*)(g_Gt + row * 512 + (idx0 & 511));
    }
    for (int i = t; i < 640; i += 256)
        s_wp1b[i] = (i < 512) ? wp1[i] : bp1[i - 512];
    for (int i = t; i < nvalid * 4; i += 256)
        s_e4[i] = e4in[base * 4 + i];
    __syncthreads();

    {
        int e = t & 127, half = t >> 7;
        float4 e4v = (e < nvalid) ? *(float4*)(s_e4 + e * 4)
                                  : make_float4(0.f, 0.f, 0.f, 0.f);
        int roff = (s_srcf[e] == src0) ? 0 : 512;
        float m0 = 0.f, m1 = 0.f, m2 = 0.f, m3 = 0.f;
        int h0 = half * 64;
#pragma unroll 4
        for (int h = h0; h < h0 + 64; h++) {
            float heh = s_wp1b[512 + h]
                      + e4v.x * s_wp1b[h]       + e4v.y * s_wp1b[128 + h]
                      + e4v.z * s_wp1b[256 + h] + e4v.w * s_wp1b[384 + h];
            heh = fmaxf(heh, 0.f);
            m0 += heh * s_G[roff + h];
            m1 += heh * s_G[roff + 128 + h];
            m2 += heh * s_G[roff + 256 + h];
            m3 += heh * s_G[roff + 384 + h];
        }
        *(float4*)(s_red + t * 4) = make_float4(m0, m1, m2, m3);
    }
    __syncthreads();
    if (t < TE) {
        int ge = base + t;
        if (ge < E_TOT) {
            float4 pa = *(float4*)(s_red + t * 4);
            float4 pb = *(float4*)(s_red + (t + 128) * 4);
            float4 cc = *(const float4*)(g_c + s_srcf[t] * 4);
            *(float4*)(g_msg + ge * 4) = make_float4(pa.x + pb.x + cc.x,
                                                     pa.y + pb.y + cc.y,
                                                     pa.z + pb.z + cc.z,
                                                     pa.w + pb.w + cc.w);
        }
    }
}

// ======== k_final: aggregate + root head ========
__global__ void k_final(const float* __restrict__ rootb, float* __restrict__ out) {
    __shared__ float red[256 * 4];
    int j = blockIdx.x, t = threadIdx.x;
    float a[4] = {0.f, 0.f, 0.f, 0.f};
    if (t < N_NODES && t != j) {
        int i = t;
        int pos = (j < i) ? j : j - 1;
        int e = i * NM1 + pos;
        float4 m = *(const float4*)(g_msg + e * 4);
        a[0] = m.x; a[1] = m.y; a[2] = m.z; a[3] = m.w;
    }
#pragma unroll
    for (int q = 0; q < 4; q++) red[t * 4 + q] = a[q];
    __syncthreads();
    for (int s = 128; s > 0; s >>= 1) {
        if (t < s)
#pragma unroll
            for (int q = 0; q < 4; q++) red[t * 4 + q] += red[(t + s) * 4 + q];
        __syncthreads();
    }
    if (t < 4) out[j * 4 + t] = red[t] + g_P[j * 4 + t] + rootb[t];
}

// ---------------- launcher ----------------
extern "C" void kernel_launch(void* const* d_in, const int* in_sizes, int n_in,
                              void* d_out, int out_size) {
    const float* roi   = (const float*)d_in[0];
    const float* bbox  = (const float*)d_in[1];
    const float* dirs  = (const float*)d_in[2];
    const float* pri   = (const float*)d_in[3];
    const float* w1    = (const float*)d_in[4];
    const float* b1    = (const float*)d_in[5];
    const float* w2    = (const float*)d_in[6];
    const float* b2    = (const float*)d_in[7];
    const float* w3    = (const float*)d_in[8];
    const float* b3    = (const float*)d_in[9];
    const float* wi    = (const float*)d_in[10];
    const float* bi    = (const float*)d_in[11];
    const float* we1   = (const float*)d_in[12];
    const float* be1   = (const float*)d_in[13];
    const float* we2   = (const float*)d_in[14];
    const float* be2   = (const float*)d_in[15];
    const float* we3   = (const float*)d_in[16];
    const float* be3   = (const float*)d_in[17];
    const float* wp1   = (const float*)d_in[18];
    const float* bp1   = (const float*)d_in[19];
    const float* wp2   = (const float*)d_in[20];
    const float* bp2   = (const float*)d_in[21];
    const float* rootw = (const float*)d_in[22];
    const float* rootb = (const float*)d_in[23];
    float* out = (float*)d_out;

    int eblk = (E_TOT + TE - 1) / TE;

    k_p0<<<2765, 256>>>(roi, w1, w3, b3, wp2, bp2, wi, rootw, bbox, dirs, we1, be1);
    k_p1<<<480, 256>>>(b1);
    k_p2<<<578, 256>>>(w2);
    k_edge_a<<<eblk, 256>>>(pri, we2, be2, we3, be3, out + 1600);   // 4th launch
    k_p3<<<200, 256>>>(b2);
    k_p4<<<216, 256>>>(bi, out + 800);
    k_edge_b<<<eblk, 256>>>(out + 1600, wp1, bp1);
    k_final<<<N_NODES, 256>>>(rootb, out);
}

// round 15
// speedup vs baseline: 1.5873x; 1.5873x over previous
#include <cuda_runtime.h>
#include <math.h>

#define N_NODES 200
#define NM1     199
#define E_TOT   39800
#define TE      128          // edge_b tile
#define TEA     64           // edge_a tile

typedef unsigned long long u64;

__device__ __forceinline__ u64 pack2(float lo, float hi) {
    u64 r; asm("mov.b64 %0,{%1,%2};" : "=l"(r) : "f"(lo), "f"(hi)); return r;
}
__device__ __forceinline__ void unpack2(u64 v, float& lo, float& hi) {
    asm("mov.b64 {%0,%1},%2;" : "=f"(lo), "=f"(hi) : "l"(v));
}
__device__ __forceinline__ void ffma2(u64& d, u64 a, u64 b) {
    asm("fma.rn.f32x2 %0,%1,%2,%0;" : "+l"(d) : "l"(a), "l"(b));
}

// ---------------- scratch ----------------
__device__ __align__(16) float g_part[16 * 200 * 512];
__device__ __align__(16) float g_wgp [4 * 257 * 512];
__device__ __align__(16) float g_h1[200 * 512];
__device__ __align__(16) float g_h2[200 * 256];
__device__ __align__(16) float g_Gt[200 * 512];      // [n][o*128+h]
__device__ __align__(16) float g_c [200 * 4];
__device__ __align__(16) float g_P [200 * 4];
__device__ __align__(16) float g_msg[E_TOT * 4];
__device__ __align__(16) float g_W3G [257 * 512];    // row 256 = bias
__device__ __align__(16) float g_W3CH[257 * 12];
__device__ __align__(16) float g_Ae[200 * 256];      // [n][u]
__device__ __align__(16) float g_Be[200 * 256];      // [n][u]
__device__ __align__(16) float g_w3b3[257 * 1024];
__device__ __align__(16) float g_wp2p[1024 * 512];

// ---------------- 256-thread GEMM tile: 64 rows x 128 cols ----------------
__device__ void gemm_tile64(const float* __restrict__ A, int lda,
                            const float* __restrict__ B, int ldb,
                            float* __restrict__ outp, int ldo, int M,
                            int col0, int row0, int k0, int k1,
                            const float* __restrict__ bias, float* sh, int modeGt) {
    float* As = sh;           // [16][68]
    float* Bs = sh + 1088;    // [16][128]
    int t = threadIdx.x;
    int tx = t & 31, ty = t >> 5;
    u64 acc[4][4];
#pragma unroll
    for (int p = 0; p < 4; p++)
#pragma unroll
        for (int c = 0; c < 4; c++) acc[p][c] = pack2(0.f, 0.f);
    int am = t >> 2;
    int ak = (t & 3) * 4;
    int bk = t >> 4;
    int bn = (t & 15) * 8;
    unsigned sa = (unsigned)__cvta_generic_to_shared(As + ty * 8);

    for (int kt = k0; kt < k1; kt += 16) {
        {
            int gr = row0 + am;
            float4 av = make_float4(0.f, 0.f, 0.f, 0.f);
            if (gr < M) av = *(const float4*)(A + (size_t)gr * lda + kt + ak);
            As[(ak + 0) * 68 + am] = av.x;
            As[(ak + 1) * 68 + am] = av.y;
            As[(ak + 2) * 68 + am] = av.z;
            As[(ak + 3) * 68 + am] = av.w;
        }
        {
            const float4* bp = (const float4*)(B + (size_t)(kt + bk) * ldb + col0 + bn);
            *(float4*)(Bs + bk * 128 + bn)     = bp[0];
            *(float4*)(Bs + bk * 128 + bn + 4) = bp[1];
        }
        __syncthreads();
#pragma unroll
        for (int kk = 0; kk < 16; kk++) {
            u64 a01, a23, a45, a67;
            asm("ld.shared.v2.u64 {%0,%1},[%2];"
                : "=l"(a01), "=l"(a23) : "r"(sa + kk * 272));
            asm("ld.shared.v2.u64 {%0,%1},[%2];"
                : "=l"(a45), "=l"(a67) : "r"(sa + kk * 272 + 16));
            float4 b4 = *(float4*)(Bs + kk * 128 + tx * 4);
            u64 bx = pack2(b4.x, b4.x), by = pack2(b4.y, b4.y);
            u64 bz = pack2(b4.z, b4.z), bw = pack2(b4.w, b4.w);
            ffma2(acc[0][0], a01, bx); ffma2(acc[1][0], a23, bx);
            ffma2(acc[2][0], a45, bx); ffma2(acc[3][0], a67, bx);
            ffma2(acc[0][1], a01, by); ffma2(acc[1][1], a23, by);
            ffma2(acc[2][1], a45, by); ffma2(acc[3][1], a67, by);
            ffma2(acc[0][2], a01, bz); ffma2(acc[1][2], a23, bz);
            ffma2(acc[2][2], a45, bz); ffma2(acc[3][2], a67, bz);
            ffma2(acc[0][3], a01, bw); ffma2(acc[1][3], a23, bw);
            ffma2(acc[2][3], a45, bw); ffma2(acc[3][3], a67, bw);
        }
        __syncthreads();
    }
#pragma unroll
    for (int p = 0; p < 4; p++) {
        int gr0 = row0 + ty * 8 + p * 2, gr1 = gr0 + 1;
#pragma unroll
        for (int c = 0; c < 4; c++) {
            float lo, hi; unpack2(acc[p][c], lo, hi);
            int col = col0 + tx * 4 + c;
            float bv = bias ? bias[col] : 0.f;
            lo += bv; hi += bv;
            int oc = modeGt ? ((col & 3) * 128 + (col >> 2)) : col;
            if (gr0 < M) outp[(size_t)gr0 * ldo + oc] = lo;
            if (gr1 < M) outp[(size_t)gr1 * ldo + oc] = hi;
        }
    }
}

// ======== k_p0: gemm1 partials | permute wp2 | prep | W3CH | w3b3 copy ========
__global__ void k_p0(const float* __restrict__ roi,  const float* __restrict__ w1,
                     const float* __restrict__ w3,   const float* __restrict__ b3,
                     const float* __restrict__ wp2,  const float* __restrict__ bp2,
                     const float* __restrict__ wi,   const float* __restrict__ rootw,
                     const float* __restrict__ bbox, const float* __restrict__ dirs,
                     const float* __restrict__ we1,  const float* __restrict__ be1) {
    __shared__ __align__(16) float sh[3136];
    int task = blockIdx.x, t = threadIdx.x;
    if (task < 256) {
        int col0 = (task & 3) * 128;
        int row0 = ((task >> 2) & 3) * 64;
        int z = task >> 4;
        gemm_tile64(roi, 2048, w1, 512, g_part + (size_t)z * 102400, 512,
                    N_NODES, col0, row0, z * 128, z * 128 + 128, nullptr, sh, 0);
    } else if (task < 1280) {
        int base = (task - 256) * 512;
#pragma unroll
        for (int q = 0; q < 2; q++) {
            int idx = base + t + q * 256;
            int i = idx >> 9, r = idx & 511;
            g_wp2p[idx] = wp2[(size_t)(r >> 2) * 4096 + i * 4 + (r & 3)];
        }
    } else if (task < 1480) {
        int n = task - 1280;
        float attr[8];
#pragma unroll
        for (int k = 0; k < 4; k++) attr[k] = bbox[n * 4 + k] * (1.0f / 1024.0f);
#pragma unroll
        for (int k = 0; k < 4; k++) attr[4 + k] = dirs[n * 4 + k];
        int u = t;
        float a = be1[u], b = 0.f;
#pragma unroll
        for (int k = 0; k < 8; k++) {
            a += attr[k] * we1[k * 256 + u];
            b += attr[k] * we1[(8 + k) * 256 + u];
        }
        g_Ae[n * 256 + u] = a;
        g_Be[n * 256 + u] = b;
    } else if (task < 1737) {
        int gr = task - 1480;
        float acc[12];
#pragma unroll
        for (int c = 0; c < 12; c++) acc[c] = 0.f;
        for (int i = t; i < 1024; i += 256) {
            float a = (gr < 256) ? w3[(size_t)gr * 1024 + i] : b3[i];
            float4 p = *(const float4*)(bp2 + i * 4);
            float4 q = *(const float4*)(wi + i * 4);
            float4 r = *(const float4*)(rootw + i * 4);
            acc[0] += a * p.x; acc[1] += a * p.y; acc[2]  += a * p.z; acc[3]  += a * p.w;
            acc[4] += a * q.x; acc[5] += a * q.y; acc[6]  += a * q.z; acc[7]  += a * q.w;
            acc[8] += a * r.x; acc[9] += a * r.y; acc[10] += a * r.z; acc[11] += a * r.w;
        }
#pragma unroll
        for (int c = 0; c < 12; c++) sh[t * 12 + c] = acc[c];
        __syncthreads();
        for (int s = 128; s > 0; s >>= 1) {
            if (t < s)
#pragma unroll
                for (int c = 0; c < 12; c++) sh[t * 12 + c] += sh[(t + s) * 12 + c];
            __syncthreads();
        }
        if (t < 12) g_W3CH[gr * 12 + t] = sh[t];
    } else {
        int idx = (task - 1737) * 256 + t;
        if (idx < 257 * 1024) {
            int row = idx >> 10, col = idx & 1023;
            g_w3b3[idx] = (row < 256) ? w3[(size_t)row * 1024 + col] : b3[col];
        }
    }
}

// ======== k_p1: h1 reduce | W3G split-K partials ========
__global__ void k_p1(const float* __restrict__ b1) {
    __shared__ __align__(16) float sh[3136];
    int task = blockIdx.x, t = threadIdx.x;
    if (task < 400) {
        int idx = task * 256 + t;
        float s = 0.f;
#pragma unroll
        for (int z = 0; z < 16; z++) s += g_part[(size_t)z * 102400 + idx];
        g_h1[idx] = fmaxf(s + b1[idx & 511], 0.f);
    } else {
        int w = task - 400;
        int col0 = (w & 3) * 128;
        int row0 = ((w >> 2) % 5) * 64;
        int z = w / 20;
        gemm_tile64(g_w3b3, 1024, g_wp2p, 512, g_wgp + (size_t)z * 131584, 512,
                    257, col0, row0, z * 256, z * 256 + 256, nullptr, sh, 0);
    }
}

// ======== k_p2: gemm2 partials | W3G reduce ========
__global__ void k_p2(const float* __restrict__ w2) {
    __shared__ __align__(16) float sh[3136];
    int task = blockIdx.x, t = threadIdx.x;
    if (task < 64) {
        int col0 = (task & 1) * 128;
        int row0 = ((task >> 1) & 3) * 64;
        int z = task >> 3;
        gemm_tile64(g_h1, 512, w2, 256, g_part + (size_t)z * 51200, 256,
                    N_NODES, col0, row0, z * 64, z * 64 + 64, nullptr, sh, 0);
    } else {
        int idx = (task - 64) * 256 + t;
        if (idx < 257 * 512) {
            float s = 0.f;
#pragma unroll
            for (int z = 0; z < 4; z++) s += g_wgp[(size_t)z * 131584 + idx];
            g_W3G[idx] = s;
        }
    }
}

// ======== k_edge_a: TEA=64 edges/block, 622 blocks (launch #4 => profiled) ========
__global__ void k_edge_a(const float* __restrict__ pri,
                         const float* __restrict__ we2, const float* __restrict__ be2,
                         const float* __restrict__ we3, const float* __restrict__ be3,
                         float* __restrict__ edge_out) {
    // ubuf: layer2 phase: s_h1[32][68] (2176 f) + s_w[32][64] (2048 f) = 4224
    //       h2 phase:     s_h2[64][68]  (4352 f)
    __shared__ __align__(16) float ubuf[4352];
    __shared__ __align__(16) float s_A[512];
    __shared__ __align__(16) float s_we3t[192];  // [w*64+v]
    __shared__ int s_src[TEA], s_dst[TEA];

    float* s_h1 = ubuf;
    float* s_w  = ubuf + 2176;
    float* s_h2 = ubuf;

    int t = threadIdx.x;
    int base = blockIdx.x * TEA;
    int src0 = base / NM1;
    int last = min(base + TEA - 1, E_TOT - 1);
    int src1 = last / NM1;

    if (t < TEA) {
        int ge = base + t;
        int i = src0, j = 0;
        if (ge < E_TOT) {
            i = ge / NM1;
            int r = ge - i * NM1;
            j = (r < i) ? r : r + 1;
        }
        s_src[t] = i; s_dst[t] = j;
    }
    if (t < 128) {
        int row = t >> 6, k4 = (t & 63) * 4;
        *(float4*)(s_A + row * 256 + k4) =
            *(const float4*)(g_Ae + (row ? src1 : src0) * 256 + k4);
    }
    if (t < 192) s_we3t[t] = we3[(t & 63) * 3 + (t >> 6)];
    __syncthreads();

    // layer2: [64e,256u]@[256u,64v], 8 chunks of 32 u; tile 4e x 4v per thread
    int tv = t & 15, teg = t >> 4;          // teg 0..15
    int v0 = tv * 4, e0 = teg * 4;
    u64 acc[2][4];
    {
        float4 b4 = *(const float4*)(be2 + v0);
        acc[0][0] = acc[1][0] = pack2(b4.x, b4.x);
        acc[0][1] = acc[1][1] = pack2(b4.y, b4.y);
        acc[0][2] = acc[1][2] = pack2(b4.z, b4.z);
        acc[0][3] = acc[1][3] = pack2(b4.w, b4.w);
    }
    unsigned hb = (unsigned)__cvta_generic_to_shared(s_h1 + e0);

    for (int uc = 0; uc < 8; uc++) {
        // h1 build: 2 float4-gathers per thread, conflict-free scalar STS
#pragma unroll
        for (int k = 0; k < 2; k++) {
            int q = t + k * 256;
            int e = q & 63;
            int u4 = (q >> 6) * 4;          // 0..28
            int U = uc * 32 + u4;
            int ge = base + e;
            float4 bv = make_float4(0.f, 0.f, 0.f, 0.f);
            float4 av = make_float4(0.f, 0.f, 0.f, 0.f);
            if (ge < E_TOT) {
                bv = *(const float4*)(g_Be + s_dst[e] * 256 + U);
                int aoff = (s_src[e] == src0) ? 0 : 256;
                av = *(const float4*)(s_A + aoff + U);
            }
            s_h1[(u4 + 0) * 68 + e] = fmaxf(av.x + bv.x, 0.f);
            s_h1[(u4 + 1) * 68 + e] = fmaxf(av.y + bv.y, 0.f);
            s_h1[(u4 + 2) * 68 + e] = fmaxf(av.z + bv.z, 0.f);
            s_h1[(u4 + 3) * 68 + e] = fmaxf(av.w + bv.w, 0.f);
        }
        // we2 chunk: 2 float4 per thread
#pragma unroll
        for (int k = 0; k < 2; k++) {
            int r = t + k * 256;
            int u = r >> 4, v4 = (r & 15) * 4;
            *(float4*)(s_w + u * 64 + v4) =
                *(const float4*)(we2 + (uc * 32 + u) * 64 + v4);
        }
        __syncthreads();
#pragma unroll 8
        for (int jj = 0; jj < 32; jj++) {
            u64 a01, a23;
            asm("ld.shared.v2.u64 {%0,%1},[%2];"
                : "=l"(a01), "=l"(a23) : "r"(hb + jj * 272));
            float4 w4 = *(float4*)(s_w + jj * 64 + v0);
            u64 bx = pack2(w4.x, w4.x), by = pack2(w4.y, w4.y);
            u64 bz = pack2(w4.z, w4.z), bw = pack2(w4.w, w4.w);
            ffma2(acc[0][0], a01, bx); ffma2(acc[1][0], a23, bx);
            ffma2(acc[0][1], a01, by); ffma2(acc[1][1], a23, by);
            ffma2(acc[0][2], a01, bz); ffma2(acc[1][2], a23, bz);
            ffma2(acc[0][3], a01, bw); ffma2(acc[1][3], a23, bw);
        }
        __syncthreads();
    }

    // h2 = relu(acc) -> s_h2[e][68]
#pragma unroll
    for (int p = 0; p < 2; p++) {
#pragma unroll
        for (int c = 0; c < 4; c++) {
            float lo, hi; unpack2(acc[p][c], lo, hi);
            s_h2[(e0 + 2 * p) * 68 + v0 + c]     = fmaxf(lo, 0.f);
            s_h2[(e0 + 2 * p + 1) * 68 + v0 + c] = fmaxf(hi, 0.f);
        }
    }
    __syncthreads();

    // layer3 sigmoid + higher_pri (thread = edge)
    if (t < TEA) {
        int e = t, ge = base + e;
        float a0 = be3[0], a1 = be3[1], a2 = be3[2];
#pragma unroll
        for (int vq = 0; vq < 64; vq += 4) {
            float4 h4 = *(float4*)(s_h2 + e * 68 + vq);
            float4 w0 = *(float4*)(s_we3t + vq);
            float4 w1 = *(float4*)(s_we3t + 64 + vq);
            float4 w2 = *(float4*)(s_we3t + 128 + vq);
            a0 += h4.x * w0.x + h4.y * w0.y + h4.z * w0.z + h4.w * w0.w;
            a1 += h4.x * w1.x + h4.y * w1.y + h4.z * w1.z + h4.w * w1.w;
            a2 += h4.x * w2.x + h4.y * w2.y + h4.z * w2.z + h4.w * w2.w;
        }
        float s0 = 1.f / (1.f + expf(-a0));
        float s1 = 1.f / (1.f + expf(-a1));
        float s2 = 1.f / (1.f + expf(-a2));
        float hp = (pri[s_src[e]] > pri[s_dst[e]]) ? 1.f : 0.f;
        if (ge < E_TOT)
            *(float4*)(edge_out + ge * 4) = make_float4(s0, s1, s2, hp);
    }
}

// ======== k_p3: h2 reduce ========
__global__ void k_p3(const float* __restrict__ b2) {
    int idx = blockIdx.x * 256 + threadIdx.x;
    float s = 0.f;
#pragma unroll
    for (int z = 0; z < 8; z++) s += g_part[(size_t)z * 51200 + idx];
    g_h2[idx] = fmaxf(s + b2[idx & 255], 0.f);
}

// ======== k_p4: Gt = (h2 @ W3G + bias) transposed | heads ========
__global__ void k_p4(const float* __restrict__ bi, float* __restrict__ out2) {
    __shared__ __align__(16) float sh[3136];
    int task = blockIdx.x, t = threadIdx.x;
    if (task < 16) {
        int col0 = (task & 3) * 128;
        int row0 = (task >> 2) * 64;
        gemm_tile64(g_h2, 256, g_W3G, 512, g_Gt, 512, N_NODES,
                    col0, row0, 0, 256, g_W3G + 256 * 512, sh, 1);
    } else {
        int n = task - 16;
        float a = g_h2[n * 256 + t];
        float4 w0  = *(const float4*)(g_W3CH + t * 12);
        float4 w1v = *(const float4*)(g_W3CH + t * 12 + 4);
        float4 w2v = *(const float4*)(g_W3CH + t * 12 + 8);
        float acc[12] = {a*w0.x, a*w0.y, a*w0.z, a*w0.w,
                         a*w1v.x, a*w1v.y, a*w1v.z, a*w1v.w,
                         a*w2v.x, a*w2v.y, a*w2v.z, a*w2v.w};
#pragma unroll
        for (int q = 0; q < 12; q++) sh[t * 12 + q] = acc[q];
        __syncthreads();
        for (int s = 128; s > 0; s >>= 1) {
            if (t < s)
#pragma unroll
                for (int q = 0; q < 12; q++) sh[t * 12 + q] += sh[(t + s) * 12 + q];
            __syncthreads();
        }
        if (t == 0) {
#pragma unroll
            for (int o = 0; o < 4; o++) {
                g_c[n * 4 + o] = sh[o] + g_W3CH[256 * 12 + o];
                float cv = sh[4 + o] + g_W3CH[256 * 12 + 4 + o] + bi[o];
                out2[n * 4 + o] = 1.f / (1.f + expf(-cv));
                g_P[n * 4 + o] = sh[8 + o] + g_W3CH[256 * 12 + 8 + o];
            }
        }
    }
}

// ======== k_edge_b: heh recompute + msg contraction ========
__global__ void k_edge_b(const float* __restrict__ e4in,
                         const float* __restrict__ wp1, const float* __restrict__ bp1) {
    __shared__ __align__(16) float s_G[1024];
    __shared__ __align__(16) float s_wp1b[640];
    __shared__ __align__(16) float s_e4[TE * 4];
    __shared__ __align__(16) float s_red[256 * 4];
    __shared__ int s_srcf[TE];

    int t = threadIdx.x;
    int base = blockIdx.x * TE;
    int src0 = base / NM1;
    int last = min(base + TE - 1, E_TOT - 1);
    int src1 = last / NM1;
    int nvalid = (E_TOT - base < TE) ? (E_TOT - base) : TE;

    if (t < TE) {
        int ge = base + t;
        s_srcf[t] = (ge < E_TOT) ? (ge / NM1) : src0;
    }
    {
        int idx0 = t * 4;
        int row = (idx0 < 512) ? src0 : src1;
        *(float4*)(s_G + idx0) = *(const float4*)(g_Gt + row * 512 + (idx0 & 511));
    }
    for (int i = t; i < 640; i += 256)
        s_wp1b[i] = (i < 512) ? wp1[i] : bp1[i - 512];
    for (int i = t; i < nvalid * 4; i += 256)
        s_e4[i] = e4in[base * 4 + i];
    __syncthreads();

    {
        int e = t & 127, half = t >> 7;
        float4 e4v = (e < nvalid) ? *(float4*)(s_e4 + e * 4)
                                  : make_float4(0.f, 0.f, 0.f, 0.f);
        int roff = (s_srcf[e] == src0) ? 0 : 512;
        float m0 = 0.f, m1 = 0.f, m2 = 0.f, m3 = 0.f;
        int h0 = half * 64;
#pragma unroll 4
        for (int h = h0; h < h0 + 64; h++) {
            float heh = s_wp1b[512 + h]
                      + e4v.x * s_wp1b[h]       + e4v.y * s_wp1b[128 + h]
                      + e4v.z * s_wp1b[256 + h] + e4v.w * s_wp1b[384 + h];
            heh = fmaxf(heh, 0.f);
            m0 += heh * s_G[roff + h];
            m1 += heh * s_G[roff + 128 + h];
            m2 += heh * s_G[roff + 256 + h];
            m3 += heh * s_G[roff + 384 + h];
        }
        *(float4*)(s_red + t * 4) = make_float4(m0, m1, m2, m3);
    }
    __syncthreads();
    if (t < TE) {
        int ge = base + t;
        if (ge < E_TOT) {
            float4 pa = *(float4*)(s_red + t * 4);
            float4 pb = *(float4*)(s_red + (t + 128) * 4);
            float4 cc = *(const float4*)(g_c + s_srcf[t] * 4);
            *(float4*)(g_msg + ge * 4) = make_float4(pa.x + pb.x + cc.x,
                                                     pa.y + pb.y + cc.y,
                                                     pa.z + pb.z + cc.z,
                                                     pa.w + pb.w + cc.w);
        }
    }
}

// ======== k_final: aggregate + root head ========
__global__ void k_final(const float* __restrict__ rootb, float* __restrict__ out) {
    __shared__ float red[256 * 4];
    int j = blockIdx.x, t = threadIdx.x;
    float a[4] = {0.f, 0.f, 0.f, 0.f};
    if (t < N_NODES && t != j) {
        int i = t;
        int pos = (j < i) ? j : j - 1;
        int e = i * NM1 + pos;
        float4 m = *(const float4*)(g_msg + e * 4);
        a[0] = m.x; a[1] = m.y; a[2] = m.z; a[3] = m.w;
    }
#pragma unroll
    for (int q = 0; q < 4; q++) red[t * 4 + q] = a[q];
    __syncthreads();
    for (int s = 128; s > 0; s >>= 1) {
        if (t < s)
#pragma unroll
            for (int q = 0; q < 4; q++) red[t * 4 + q] += red[(t + s) * 4 + q];
        __syncthreads();
    }
    if (t < 4) out[j * 4 + t] = red[t] + g_P[j * 4 + t] + rootb[t];
}

// ---------------- launcher ----------------
extern "C" void kernel_launch(void* const* d_in, const int* in_sizes, int n_in,
                              void* d_out, int out_size) {
    const float* roi   = (const float*)d_in[0];
    const float* bbox  = (const float*)d_in[1];
    const float* dirs  = (const float*)d_in[2];
    const float* pri   = (const float*)d_in[3];
    const float* w1    = (const float*)d_in[4];
    const float* b1    = (const float*)d_in[5];
    const float* w2    = (const float*)d_in[6];
    const float* b2    = (const float*)d_in[7];
    const float* w3    = (const float*)d_in[8];
    const float* b3    = (const float*)d_in[9];
    const float* wi    = (const float*)d_in[10];
    const float* bi    = (const float*)d_in[11];
    const float* we1   = (const float*)d_in[12];
    const float* be1   = (const float*)d_in[13];
    const float* we2   = (const float*)d_in[14];
    const float* be2   = (const float*)d_in[15];
    const float* we3   = (const float*)d_in[16];
    const float* be3   = (const float*)d_in[17];
    const float* wp1   = (const float*)d_in[18];
    const float* bp1   = (const float*)d_in[19];
    const float* wp2   = (const float*)d_in[20];
    const float* bp2   = (const float*)d_in[21];
    const float* rootw = (const float*)d_in[22];
    const float* rootb = (const float*)d_in[23];
    float* out = (float*)d_out;

    int eblkA = (E_TOT + TEA - 1) / TEA;   // 622
    int eblkB = (E_TOT + TE - 1) / TE;     // 311

    k_p0<<<2765, 256>>>(roi, w1, w3, b3, wp2, bp2, wi, rootw, bbox, dirs, we1, be1);
    k_p1<<<480, 256>>>(b1);
    k_p2<<<578, 256>>>(w2);
    k_edge_a<<<eblkA, 256>>>(pri, we2, be2, we3, be3, out + 1600);   // 4th launch
    k_p3<<<200, 256>>>(b2);
    k_p4<<<216, 256>>>(bi, out + 800);
    k_edge_b<<<eblkB, 256>>>(out + 1600, wp1, bp1);
    k_final<<<N_NODES, 256>>>(rootb, out);
}